// round 3
// baseline (speedup 1.0000x reference)
#include <cuda_runtime.h>
#include <math.h>

#define RPB 64       // rows per block
#define TPB 256      // threads per block (8 warps)
#define WSTRIDE 132  // padded row stride (floats) for sZ1

// Shared layout (floats), 16B-aligned offsets:
#define OFF_Z1   0                        // [64][132] = 8448 (also input staging area)
#define OFF_H1   (OFF_Z1  + RPB*WSTRIDE)  // [64][12]  = 768
#define OFF_SE   (OFF_H1  + 768)          // [64][18]  = 1152
#define OFF_DV   (OFF_SE  + 1152)         // [64][6]   = 384
#define OFF_OUT  (OFF_DV  + 384)          // [64][18]  = 1152 (s_next staging)
#define OFF_W1   (OFF_OUT + 1152)         // [128][12] = 1536
#define OFF_W3   (OFF_W1  + 1536)         // [6][128]  = 768
#define OFF_WIH  (OFF_W3  + 768)          // [12][21]  = 252 pad 256
#define OFF_WHH  (OFF_WIH + 256)          // [12][12]  = 144
#define SMEM_FLOATS (OFF_WHH + 144 + 16)
#define SMEM_BYTES  (SMEM_FLOATS * 4)

// staging offsets inside the Z1 region (dead until phase 2)
#define STG_S  (OFF_Z1)          // [64][18] = 1152
#define STG_A  (OFF_Z1 + 1152)   // [64][6]  = 384
#define STG_H0 (OFF_Z1 + 1536)   // [64][12] = 768

__device__ __forceinline__ float lrelu(float z) { return z >= 0.0f ? z : 0.1f * z; }

__device__ __forceinline__ unsigned long long ffma2(unsigned long long a,
                                                    unsigned long long b,
                                                    unsigned long long c) {
    unsigned long long d;
    asm("fma.rn.f32x2 %0, %1, %2, %3;" : "=l"(d) : "l"(a), "l"(b), "l"(c));
    return d;
}

__device__ __forceinline__ float unpack_sum(unsigned long long u) {
    float2 f;
    asm("mov.b64 {%0, %1}, %2;" : "=f"(f.x), "=f"(f.y) : "l"(u));
    return f.x + f.y;
}

__global__ __launch_bounds__(TPB, 2)
void auv_step_kernel(const float* __restrict__ s,
                     const float* __restrict__ a,
                     const float* __restrict__ h0,
                     const float* __restrict__ Wih,
                     const float* __restrict__ Whh,
                     const float* __restrict__ W1,
                     const float* __restrict__ W2,
                     const float* __restrict__ W3,
                     float* __restrict__ out,
                     int Krows)
{
    extern __shared__ float sm[];
    float* sZ1  = sm + OFF_Z1;
    float* sH1  = sm + OFF_H1;
    float* sSE  = sm + OFF_SE;
    float* sDV  = sm + OFF_DV;
    float* sOut = sm + OFF_OUT;
    float* sW1  = sm + OFF_W1;
    float* sW3  = sm + OFF_W3;
    float* sWih = sm + OFF_WIH;
    float* sWhh = sm + OFF_WHH;

    const int tid = threadIdx.x;
    const long long rowBase = (long long)blockIdx.x * RPB;
    const long long Kll = (long long)Krows;

    // ---- cooperative staging (coalesced float4); W2 deliberately NOT staged ----
    {
        for (int i = tid; i < 384; i += TPB) ((float4*)sW1)[i] = ((const float4*)W1)[i];
        for (int i = tid; i < 192; i += TPB) ((float4*)sW3)[i] = ((const float4*)W3)[i];
        if (tid < 63) ((float4*)sWih)[tid] = ((const float4*)Wih)[tid];
        if (tid < 36) ((float4*)sWhh)[tid] = ((const float4*)Whh)[tid];
        const float4* sv = (const float4*)(s  + rowBase * 18);
        const float4* av = (const float4*)(a  + rowBase * 6);
        const float4* hv = (const float4*)(h0 + rowBase * 12);
        for (int i = tid; i < 288; i += TPB) ((float4*)(sm + STG_S))[i]  = sv[i];
        if (tid < 96)  ((float4*)(sm + STG_A))[tid]  = av[tid];
        for (int i = tid; i < 192; i += TPB) ((float4*)(sm + STG_H0))[i] = hv[i];
    }
    __syncthreads();

    // ---- phase 1: RNN cell (h1) + SE(3) per-row precompute (64 threads) ----
    if (tid < RPB) {
        const int r = tid;
        const float* Sr  = sm + STG_S  + r * 18;
        const float* Ar  = sm + STG_A  + r * 6;
        const float* H0r = sm + STG_H0 + r * 12;

        float x[21];
        #pragma unroll
        for (int i = 0; i < 15; i++) x[i] = Sr[3 + i];
        #pragma unroll
        for (int i = 0; i < 6; i++) x[15 + i] = Ar[i];
        float h0r[12];
        #pragma unroll
        for (int i = 0; i < 12; i++) h0r[i] = H0r[i];

        float h1r[12];
        #pragma unroll
        for (int j = 0; j < 12; j++) {
            float acc = 0.0f;
            #pragma unroll
            for (int i = 0; i < 21; i++) acc += x[i] * sWih[j * 21 + i];
            #pragma unroll
            for (int i = 0; i < 12; i++) acc += h0r[i] * sWhh[j * 12 + i];
            h1r[j] = tanhf(acc);
        }

        // SE(3)
        const float p0 = Sr[0], p1 = Sr[1], p2 = Sr[2];
        float R[9];
        #pragma unroll
        for (int i = 0; i < 9; i++) R[i] = Sr[3 + i];
        float v[6];
        #pragma unroll
        for (int i = 0; i < 6; i++) v[i] = Sr[12 + i];

        const float DT = 0.1f;
        const float rho0 = v[0] * DT, rho1 = v[1] * DT, rho2 = v[2] * DT;
        const float px = v[3] * DT, py = v[4] * DT, pz = v[5] * DT;
        const float th2 = px * px + py * py + pz * pz;
        const bool small = th2 < 1e-8f;
        const float th2s = small ? 1.0f : th2;
        const float th = sqrtf(th2s);
        const float sth = sinf(th), cth = cosf(th);
        const float A = small ? (1.0f - th2 * (1.0f / 6.0f))  : (sth / th);
        const float B = small ? (0.5f - th2 * (1.0f / 24.0f)) : ((1.0f - cth) / th2s);
        const float C = small ? (1.0f / 6.0f - th2 * (1.0f / 120.0f)) : ((th - sth) / (th2s * th));

        const float S[9]  = {0.0f, -pz, py,  pz, 0.0f, -px,  -py, px, 0.0f};
        float S2[9];
        S2[0] = -(py * py + pz * pz); S2[1] = px * py;              S2[2] = px * pz;
        S2[3] = px * py;              S2[4] = -(px * px + pz * pz); S2[5] = py * pz;
        S2[6] = px * pz;              S2[7] = py * pz;              S2[8] = -(px * px + py * py);

        float Re[9], Vm[9];
        #pragma unroll
        for (int i = 0; i < 9; i++) {
            const float I = (i == 0 || i == 4 || i == 8) ? 1.0f : 0.0f;
            Re[i] = I + A * S[i] + B * S2[i];
            Vm[i] = I + B * S[i] + C * S2[i];
        }
        const float pe0 = Vm[0] * rho0 + Vm[1] * rho1 + Vm[2] * rho2;
        const float pe1 = Vm[3] * rho0 + Vm[4] * rho1 + Vm[5] * rho2;
        const float pe2 = Vm[6] * rho0 + Vm[7] * rho1 + Vm[8] * rho2;

        float Rn[9];
        #pragma unroll
        for (int i = 0; i < 3; i++)
            #pragma unroll
            for (int j = 0; j < 3; j++)
                Rn[i * 3 + j] = R[i * 3 + 0] * Re[0 + j] + R[i * 3 + 1] * Re[3 + j] + R[i * 3 + 2] * Re[6 + j];

        const float pn0 = R[0] * pe0 + R[1] * pe1 + R[2] * pe2 + p0;
        const float pn1 = R[3] * pe0 + R[4] * pe1 + R[5] * pe2 + p1;
        const float pn2 = R[6] * pe0 + R[7] * pe1 + R[8] * pe2 + p2;

        float Ri[9] = {Rn[0], Rn[3], Rn[6], Rn[1], Rn[4], Rn[7], Rn[2], Rn[5], Rn[8]};
        const float pi0 = -(Ri[0] * pn0 + Ri[1] * pn1 + Ri[2] * pn2);
        const float pi1 = -(Ri[3] * pn0 + Ri[4] * pn1 + Ri[5] * pn2);
        const float pi2 = -(Ri[6] * pn0 + Ri[7] * pn1 + Ri[8] * pn2);

        // vI = Ad(R, p) @ v
        const float u0 = R[0] * v[0] + R[1] * v[1] + R[2] * v[2];
        const float u1 = R[3] * v[0] + R[4] * v[1] + R[5] * v[2];
        const float u2 = R[6] * v[0] + R[7] * v[1] + R[8] * v[2];
        const float w0 = R[0] * v[3] + R[1] * v[4] + R[2] * v[5];
        const float w1 = R[3] * v[3] + R[4] * v[4] + R[5] * v[5];
        const float w2 = R[6] * v[3] + R[7] * v[4] + R[8] * v[5];
        const float t0 = u0 + (p1 * w2 - p2 * w1);
        const float t1 = u1 + (p2 * w0 - p0 * w2);
        const float t2 = u2 + (p0 * w1 - p1 * w0);

        // write AFTER all staged reads of this row are done (they are: all in regs)
        #pragma unroll
        for (int j = 0; j < 12; j++) sH1[r * 12 + j] = h1r[j];

        float* se = sSE + r * 18;
        #pragma unroll
        for (int i = 0; i < 9; i++) se[i] = Ri[i];
        se[9]  = pi0; se[10] = pi1; se[11] = pi2;
        se[12] = t0;  se[13] = t1;  se[14] = t2;
        se[15] = w0;  se[16] = w1;  se[17] = w2;

        float* o = sOut + r * 18;
        o[0] = pn0; o[1] = pn1; o[2] = pn2;
        #pragma unroll
        for (int i = 0; i < 9; i++) o[3 + i] = Rn[i];
    }
    __syncthreads();

    // ---- phase 2: z1 = lrelu(h1 @ W1^T)  [64 rows][128 cols], packed over 12-dim ----
    {
        const int c = tid & 127;
        const unsigned long long* wp = (const unsigned long long*)(sW1 + c * 12); // 48B aligned
        unsigned long long w[6];
        #pragma unroll
        for (int j = 0; j < 6; j++) w[j] = wp[j];
        #pragma unroll
        for (int r = tid >> 7; r < RPB; r += 2) {
            const unsigned long long* hp = (const unsigned long long*)(sH1 + r * 12);
            unsigned long long acc = 0ull;
            #pragma unroll
            for (int j = 0; j < 6; j++) acc = ffma2(hp[j], w[j], acc);
            sZ1[r * WSTRIDE + c] = lrelu(unpack_sum(acc));
        }
    }
    __syncthreads();

    // ---- phase 3: z2 = lrelu(z1 @ W2^T), W2 streamed from L1 via LDG; dv = z2 @ W3^T ----
    {
        const int warp = tid >> 5;
        const int lane = tid & 31;
        const int r0   = warp * 8;                 // 8 rows per warp, 8 warps = 64 rows
        // cols c_j = lane + 32*j, j<4

        unsigned long long acc2[8][4];
        #pragma unroll
        for (int i = 0; i < 8; i++)
            #pragma unroll
            for (int j = 0; j < 4; j++) acc2[i][j] = 0ull;

        const float4* W2v = (const float4*)W2;     // row-major [128][128]

        #pragma unroll 2
        for (int k = 0; k < 128; k += 4) {
            ulonglong2 rv[8], cv[4];
            #pragma unroll
            for (int i = 0; i < 8; i++)
                rv[i] = *(const ulonglong2*)(sZ1 + (r0 + i) * WSTRIDE + k);   // broadcast LDS
            #pragma unroll
            for (int j = 0; j < 4; j++) {
                float4 w4 = __ldg(&W2v[(lane + 32 * j) * 32 + (k >> 2)]);     // L1-resident
                cv[j] = *(ulonglong2*)&w4;
            }
            #pragma unroll
            for (int i = 0; i < 8; i++)
                #pragma unroll
                for (int j = 0; j < 4; j++) {
                    acc2[i][j] = ffma2(rv[i].x, cv[j].x, acc2[i][j]);
                    acc2[i][j] = ffma2(rv[i].y, cv[j].y, acc2[i][j]);
                }
        }

        float z2[8][4];
        #pragma unroll
        for (int i = 0; i < 8; i++)
            #pragma unroll
            for (int j = 0; j < 4; j++) z2[i][j] = lrelu(unpack_sum(acc2[i][j]));

        // dv partials over this thread's 4 cols
        float pd[8][6];
        #pragma unroll
        for (int i = 0; i < 8; i++)
            #pragma unroll
            for (int d = 0; d < 6; d++) pd[i][d] = 0.0f;

        #pragma unroll
        for (int j = 0; j < 4; j++) {
            const int c = lane + 32 * j;
            #pragma unroll
            for (int d = 0; d < 6; d++) {
                const float w3 = sW3[d * 128 + c];
                #pragma unroll
                for (int i = 0; i < 8; i++) pd[i][d] += z2[i][j] * w3;
            }
        }

        #pragma unroll
        for (int m = 1; m < 32; m <<= 1)
            #pragma unroll
            for (int i = 0; i < 8; i++)
                #pragma unroll
                for (int d = 0; d < 6; d++)
                    pd[i][d] += __shfl_xor_sync(0xffffffffu, pd[i][d], m);

        if (lane == 0) {
            #pragma unroll
            for (int i = 0; i < 8; i++)
                #pragma unroll
                for (int d = 0; d < 6; d++) sDV[(r0 + i) * 6 + d] = pd[i][d];
        }
    }
    __syncthreads();

    // ---- phase 4: v_next = Ad(Rinv, pinv) @ (vI + dv) ----
    if (tid < RPB) {
        const int r = tid;
        const float* se  = sSE + r * 18;
        const float* dvp = sDV + r * 6;

        float w6[6];
        #pragma unroll
        for (int i = 0; i < 6; i++) w6[i] = se[12 + i] + dvp[i];

        const float* Ri = se;
        const float pi0 = se[9], pi1 = se[10], pi2 = se[11];

        const float a0 = Ri[0] * w6[0] + Ri[1] * w6[1] + Ri[2] * w6[2];
        const float a1 = Ri[3] * w6[0] + Ri[4] * w6[1] + Ri[5] * w6[2];
        const float a2 = Ri[6] * w6[0] + Ri[7] * w6[1] + Ri[8] * w6[2];
        const float b0 = Ri[0] * w6[3] + Ri[1] * w6[4] + Ri[2] * w6[5];
        const float b1 = Ri[3] * w6[3] + Ri[4] * w6[4] + Ri[5] * w6[5];
        const float b2 = Ri[6] * w6[3] + Ri[7] * w6[4] + Ri[8] * w6[5];

        float* o = sOut + r * 18;
        o[12] = a0 + (pi1 * b2 - pi2 * b1);
        o[13] = a1 + (pi2 * b0 - pi0 * b2);
        o[14] = a2 + (pi0 * b1 - pi1 * b0);
        o[15] = b0;
        o[16] = b1;
        o[17] = b2;
    }
    __syncthreads();

    // ---- phase 5: coalesced vectorized dump ----
    {
        float4* d0 = (float4*)(out + rowBase * 18);               // s_next: 1152 floats
        float4* d1 = (float4*)(out + Kll * 18 + rowBase * 12);    // hN:      768 floats
        float4* d2 = (float4*)(out + Kll * 30 + rowBase * 6);     // dv:      384 floats
        const float4* s0 = (const float4*)sOut;
        const float4* s1 = (const float4*)sH1;
        const float4* s2 = (const float4*)sDV;
        for (int i = tid; i < 288; i += TPB) d0[i] = s0[i];
        if (tid < 192) d1[tid] = s1[tid];
        if (tid < 96)  d2[tid] = s2[tid];
    }
}

extern "C" void kernel_launch(void* const* d_in, const int* in_sizes, int n_in,
                              void* d_out, int out_size)
{
    const float* s   = (const float*)d_in[0];
    const float* a   = (const float*)d_in[1];
    const float* h0  = (const float*)d_in[2];
    const float* Wih = (const float*)d_in[3];
    const float* Whh = (const float*)d_in[4];
    const float* W1  = (const float*)d_in[5];
    const float* W2  = (const float*)d_in[6];
    const float* W3  = (const float*)d_in[7];
    float* out = (float*)d_out;

    const int Krows = in_sizes[0] / 18;      // s is [K,1,18]
    const int nblk = Krows / RPB;

    cudaFuncSetAttribute(auv_step_kernel,
                         cudaFuncAttributeMaxDynamicSharedMemorySize, SMEM_BYTES);
    auv_step_kernel<<<nblk, TPB, SMEM_BYTES>>>(s, a, h0, Wih, Whh, W1, W2, W3, out, Krows);
}

// round 4
// speedup vs baseline: 2.1456x; 2.1456x over previous
#include <cuda_runtime.h>
#include <math.h>

#define RPB 64       // rows per block
#define TPB 256      // threads per block (8 warps)
#define WSTRIDE 132  // padded row stride (floats): 528B, 16B-aligned, conflict-free LDS.128

// Shared layout (floats), 16B-aligned offsets:
#define OFF_W2   0                         // [128][132] = 16896
#define OFF_Z1   (OFF_W2  + 128*WSTRIDE)   // [64][132]  = 8448  (staging overlay before phase 2)
#define OFF_H1   (OFF_Z1  + RPB*WSTRIDE)   // [64][12]   = 768
#define OFF_SE   (OFF_H1  + 768)           // [64][18]   = 1152
#define OFF_DV   (OFF_SE  + 1152)          // [64][6]    = 384
#define OFF_WIH  (OFF_DV  + 384)           // [12][21]   = 252 pad 256
#define OFF_WHH  (OFF_WIH + 256)           // [12][12]   = 144
#define SMEM_FLOATS (OFF_WHH + 144)
#define SMEM_BYTES  (SMEM_FLOATS * 4)      // 112,192 B -> 2 CTAs = 219 KiB <= 228 KiB

// staging offsets inside the Z1 region (dead until phase 2)
#define STG_S  (OFF_Z1)          // [64][18] = 1152
#define STG_A  (OFF_Z1 + 1152)   // [64][6]  = 384
#define STG_H0 (OFF_Z1 + 1536)   // [64][12] = 768

__device__ __forceinline__ float lrelu(float z) { return z >= 0.0f ? z : 0.1f * z; }

__device__ __forceinline__ unsigned long long ffma2(unsigned long long a,
                                                    unsigned long long b,
                                                    unsigned long long c) {
    unsigned long long d;
    asm("fma.rn.f32x2 %0, %1, %2, %3;" : "=l"(d) : "l"(a), "l"(b), "l"(c));
    return d;
}

__device__ __forceinline__ float unpack_sum(unsigned long long u) {
    float2 f;
    asm("mov.b64 {%0, %1}, %2;" : "=f"(f.x), "=f"(f.y) : "l"(u));
    return f.x + f.y;
}

__global__ __launch_bounds__(TPB, 2)
void auv_step_kernel(const float* __restrict__ s,
                     const float* __restrict__ a,
                     const float* __restrict__ h0,
                     const float* __restrict__ Wih,
                     const float* __restrict__ Whh,
                     const float* __restrict__ W1,
                     const float* __restrict__ W2,
                     const float* __restrict__ W3,
                     float* __restrict__ out,
                     int Krows)
{
    extern __shared__ float sm[];
    float* sW2  = sm + OFF_W2;
    float* sZ1  = sm + OFF_Z1;
    float* sH1  = sm + OFF_H1;
    float* sSE  = sm + OFF_SE;
    float* sDV  = sm + OFF_DV;
    float* sWih = sm + OFF_WIH;
    float* sWhh = sm + OFF_WHH;

    const int tid = threadIdx.x;
    const long long rowBase = (long long)blockIdx.x * RPB;
    const long long Kll = (long long)Krows;

    // ---- staging: W2 into padded smem, small weights, per-row inputs ----
    {
        const float4* W2v = (const float4*)W2;
        #pragma unroll
        for (int i = tid; i < 4096; i += TPB) {           // 128x128 floats = 4096 float4
            float4 v = W2v[i];
            const int row = i >> 5, c4 = i & 31;
            *(float4*)(sW2 + row * WSTRIDE + c4 * 4) = v;
        }
        if (tid < 63) ((float4*)sWih)[tid] = ((const float4*)Wih)[tid];   // 252 floats
        if (tid < 36) ((float4*)sWhh)[tid] = ((const float4*)Whh)[tid];   // 144 floats
        const float4* sv = (const float4*)(s  + rowBase * 18);
        const float4* av = (const float4*)(a  + rowBase * 6);
        const float4* hv = (const float4*)(h0 + rowBase * 12);
        for (int i = tid; i < 288; i += TPB) ((float4*)(sm + STG_S))[i] = sv[i];
        if (tid < 96)  ((float4*)(sm + STG_A))[tid]  = av[tid];
        if (tid < 192) ((float4*)(sm + STG_H0))[tid] = hv[tid];
    }
    __syncthreads();

    // ---- phase 1 (parallel split): tid<64 -> RNN h1 ; 64<=tid<128 -> SE(3) ----
    if (tid < RPB) {
        const int r = tid;
        const float* Sr  = sm + STG_S  + r * 18;
        const float* Ar  = sm + STG_A  + r * 6;
        const float* H0r = sm + STG_H0 + r * 12;

        float x[21];
        #pragma unroll
        for (int i = 0; i < 15; i++) x[i] = Sr[3 + i];
        #pragma unroll
        for (int i = 0; i < 6; i++) x[15 + i] = Ar[i];
        float h0r[12];
        #pragma unroll
        for (int i = 0; i < 12; i++) h0r[i] = H0r[i];

        #pragma unroll
        for (int j = 0; j < 12; j++) {
            float acc = 0.0f;
            #pragma unroll
            for (int i = 0; i < 21; i++) acc += x[i] * sWih[j * 21 + i];
            #pragma unroll
            for (int i = 0; i < 12; i++) acc += h0r[i] * sWhh[j * 12 + i];
            sH1[r * 12 + j] = tanhf(acc);
        }
    } else if (tid < 2 * RPB) {
        const int r = tid - RPB;
        const long long g = rowBase + r;
        const float* Sr = sm + STG_S + r * 18;

        const float p0 = Sr[0], p1 = Sr[1], p2 = Sr[2];
        float R[9];
        #pragma unroll
        for (int i = 0; i < 9; i++) R[i] = Sr[3 + i];
        float v[6];
        #pragma unroll
        for (int i = 0; i < 6; i++) v[i] = Sr[12 + i];

        const float DT = 0.1f;
        const float rho0 = v[0] * DT, rho1 = v[1] * DT, rho2 = v[2] * DT;
        const float px = v[3] * DT, py = v[4] * DT, pz = v[5] * DT;
        const float th2 = px * px + py * py + pz * pz;
        const bool small = th2 < 1e-8f;
        const float th2s = small ? 1.0f : th2;
        const float th = sqrtf(th2s);
        const float sth = sinf(th), cth = cosf(th);
        const float A = small ? (1.0f - th2 * (1.0f / 6.0f))  : (sth / th);
        const float B = small ? (0.5f - th2 * (1.0f / 24.0f)) : ((1.0f - cth) / th2s);
        const float C = small ? (1.0f / 6.0f - th2 * (1.0f / 120.0f)) : ((th - sth) / (th2s * th));

        const float S[9]  = {0.0f, -pz, py,  pz, 0.0f, -px,  -py, px, 0.0f};
        float S2[9];
        S2[0] = -(py * py + pz * pz); S2[1] = px * py;              S2[2] = px * pz;
        S2[3] = px * py;              S2[4] = -(px * px + pz * pz); S2[5] = py * pz;
        S2[6] = px * pz;              S2[7] = py * pz;              S2[8] = -(px * px + py * py);

        float Re[9], Vm[9];
        #pragma unroll
        for (int i = 0; i < 9; i++) {
            const float I = (i == 0 || i == 4 || i == 8) ? 1.0f : 0.0f;
            Re[i] = I + A * S[i] + B * S2[i];
            Vm[i] = I + B * S[i] + C * S2[i];
        }
        const float pe0 = Vm[0] * rho0 + Vm[1] * rho1 + Vm[2] * rho2;
        const float pe1 = Vm[3] * rho0 + Vm[4] * rho1 + Vm[5] * rho2;
        const float pe2 = Vm[6] * rho0 + Vm[7] * rho1 + Vm[8] * rho2;

        float Rn[9];
        #pragma unroll
        for (int i = 0; i < 3; i++)
            #pragma unroll
            for (int j = 0; j < 3; j++)
                Rn[i * 3 + j] = R[i * 3 + 0] * Re[0 + j] + R[i * 3 + 1] * Re[3 + j] + R[i * 3 + 2] * Re[6 + j];

        const float pn0 = R[0] * pe0 + R[1] * pe1 + R[2] * pe2 + p0;
        const float pn1 = R[3] * pe0 + R[4] * pe1 + R[5] * pe2 + p1;
        const float pn2 = R[6] * pe0 + R[7] * pe1 + R[8] * pe2 + p2;

        float Ri[9] = {Rn[0], Rn[3], Rn[6], Rn[1], Rn[4], Rn[7], Rn[2], Rn[5], Rn[8]};
        const float pi0 = -(Ri[0] * pn0 + Ri[1] * pn1 + Ri[2] * pn2);
        const float pi1 = -(Ri[3] * pn0 + Ri[4] * pn1 + Ri[5] * pn2);
        const float pi2 = -(Ri[6] * pn0 + Ri[7] * pn1 + Ri[8] * pn2);

        // vI = Ad(R, p) @ v
        const float u0 = R[0] * v[0] + R[1] * v[1] + R[2] * v[2];
        const float u1 = R[3] * v[0] + R[4] * v[1] + R[5] * v[2];
        const float u2 = R[6] * v[0] + R[7] * v[1] + R[8] * v[2];
        const float w0 = R[0] * v[3] + R[1] * v[4] + R[2] * v[5];
        const float w1 = R[3] * v[3] + R[4] * v[4] + R[5] * v[5];
        const float w2 = R[6] * v[3] + R[7] * v[4] + R[8] * v[5];
        const float t0 = u0 + (p1 * w2 - p2 * w1);
        const float t1 = u1 + (p2 * w0 - p0 * w2);
        const float t2 = u2 + (p0 * w1 - p1 * w0);

        float* se = sSE + r * 18;
        #pragma unroll
        for (int i = 0; i < 9; i++) se[i] = Ri[i];
        se[9]  = pi0; se[10] = pi1; se[11] = pi2;
        se[12] = t0;  se[13] = t1;  se[14] = t2;
        se[15] = w0;  se[16] = w1;  se[17] = w2;

        // s_next[0:12] directly to gmem (64 threads, small)
        float* o = out + g * 18;
        o[0] = pn0; o[1] = pn1; o[2] = pn2;
        #pragma unroll
        for (int i = 0; i < 9; i++) o[3 + i] = Rn[i];
    }
    __syncthreads();

    // ---- phase 2: z1 = lrelu(h1 @ W1^T)  [64 rows][128 cols]; W1 via __ldg ----
    {
        const int c = tid & 127;
        const float4* w1v = (const float4*)(W1 + c * 12);   // 48B-aligned
        float4 wa = __ldg(w1v), wb = __ldg(w1v + 1), wc = __ldg(w1v + 2);
        unsigned long long w[6];
        w[0] = *(unsigned long long*)&wa.x;  w[1] = *(unsigned long long*)&wa.z;
        w[2] = *(unsigned long long*)&wb.x;  w[3] = *(unsigned long long*)&wb.z;
        w[4] = *(unsigned long long*)&wc.x;  w[5] = *(unsigned long long*)&wc.z;
        #pragma unroll
        for (int r = tid >> 7; r < RPB; r += 2) {
            const unsigned long long* hp = (const unsigned long long*)(sH1 + r * 12);
            unsigned long long acc = 0ull;
            #pragma unroll
            for (int j = 0; j < 6; j++) acc = ffma2(hp[j], w[j], acc);
            sZ1[r * WSTRIDE + c] = lrelu(unpack_sum(acc));
        }
    }
    __syncthreads();

    // ---- phase 3: z2 = lrelu(z1 @ W2^T) (smem W2, packed f32x2); dv = z2 @ W3^T ----
    {
        const int warp = tid >> 5;
        const int lane = tid & 31;
        const int r0   = warp * 8;                 // 8 rows per warp, 8 warps = 64 rows

        unsigned long long acc2[8][4];
        #pragma unroll
        for (int i = 0; i < 8; i++)
            #pragma unroll
            for (int j = 0; j < 4; j++) acc2[i][j] = 0ull;

        #pragma unroll 2
        for (int k = 0; k < 128; k += 4) {
            ulonglong2 rv[8], cv[4];
            #pragma unroll
            for (int i = 0; i < 8; i++)
                rv[i] = *(const ulonglong2*)(sZ1 + (r0 + i) * WSTRIDE + k);   // broadcast LDS
            #pragma unroll
            for (int j = 0; j < 4; j++)
                cv[j] = *(const ulonglong2*)(sW2 + (lane + 32 * j) * WSTRIDE + k);
            #pragma unroll
            for (int i = 0; i < 8; i++)
                #pragma unroll
                for (int j = 0; j < 4; j++) {
                    acc2[i][j] = ffma2(rv[i].x, cv[j].x, acc2[i][j]);
                    acc2[i][j] = ffma2(rv[i].y, cv[j].y, acc2[i][j]);
                }
        }

        float z2[8][4];
        #pragma unroll
        for (int i = 0; i < 8; i++)
            #pragma unroll
            for (int j = 0; j < 4; j++) z2[i][j] = lrelu(unpack_sum(acc2[i][j]));

        // dv partials; W3 via __ldg (coalesced: lane stride 1)
        float pd[8][6];
        #pragma unroll
        for (int i = 0; i < 8; i++)
            #pragma unroll
            for (int d = 0; d < 6; d++) pd[i][d] = 0.0f;

        #pragma unroll
        for (int j = 0; j < 4; j++) {
            const int c = lane + 32 * j;
            #pragma unroll
            for (int d = 0; d < 6; d++) {
                const float w3 = __ldg(W3 + d * 128 + c);
                #pragma unroll
                for (int i = 0; i < 8; i++) pd[i][d] += z2[i][j] * w3;
            }
        }

        #pragma unroll
        for (int m = 1; m < 32; m <<= 1)
            #pragma unroll
            for (int i = 0; i < 8; i++)
                #pragma unroll
                for (int d = 0; d < 6; d++)
                    pd[i][d] += __shfl_xor_sync(0xffffffffu, pd[i][d], m);

        if (lane == 0) {
            #pragma unroll
            for (int i = 0; i < 8; i++)
                #pragma unroll
                for (int d = 0; d < 6; d++) sDV[(r0 + i) * 6 + d] = pd[i][d];
        }
    }
    __syncthreads();

    // ---- phase 4: v_next ; phase 5: coalesced hN/dv dump (concurrent) ----
    if (tid < RPB) {
        const int r = tid;
        const long long g = rowBase + r;
        const float* se  = sSE + r * 18;
        const float* dvp = sDV + r * 6;

        float w6[6];
        #pragma unroll
        for (int i = 0; i < 6; i++) w6[i] = se[12 + i] + dvp[i];

        const float* Ri = se;
        const float pi0 = se[9], pi1 = se[10], pi2 = se[11];

        const float a0 = Ri[0] * w6[0] + Ri[1] * w6[1] + Ri[2] * w6[2];
        const float a1 = Ri[3] * w6[0] + Ri[4] * w6[1] + Ri[5] * w6[2];
        const float a2 = Ri[6] * w6[0] + Ri[7] * w6[1] + Ri[8] * w6[2];
        const float b0 = Ri[0] * w6[3] + Ri[1] * w6[4] + Ri[2] * w6[5];
        const float b1 = Ri[3] * w6[3] + Ri[4] * w6[4] + Ri[5] * w6[5];
        const float b2 = Ri[6] * w6[3] + Ri[7] * w6[4] + Ri[8] * w6[5];

        float* o = out + g * 18;
        o[12] = a0 + (pi1 * b2 - pi2 * b1);
        o[13] = a1 + (pi2 * b0 - pi0 * b2);
        o[14] = a2 + (pi0 * b1 - pi1 * b0);
        o[15] = b0;
        o[16] = b1;
        o[17] = b2;
    } else {
        const int t = tid - RPB;   // 0..191
        float4* d1 = (float4*)(out + Kll * 18 + rowBase * 12);    // hN: 192 float4
        if (t < 96) {
            float4* d2 = (float4*)(out + Kll * 30 + rowBase * 6); // dv: 96 float4
            d2[t] = ((const float4*)sDV)[t];
        }
        d1[t] = ((const float4*)sH1)[t];
    }
}

extern "C" void kernel_launch(void* const* d_in, const int* in_sizes, int n_in,
                              void* d_out, int out_size)
{
    const float* s   = (const float*)d_in[0];
    const float* a   = (const float*)d_in[1];
    const float* h0  = (const float*)d_in[2];
    const float* Wih = (const float*)d_in[3];
    const float* Whh = (const float*)d_in[4];
    const float* W1  = (const float*)d_in[5];
    const float* W2  = (const float*)d_in[6];
    const float* W3  = (const float*)d_in[7];
    float* out = (float*)d_out;

    const int Krows = in_sizes[0] / 18;      // s is [K,1,18]
    const int nblk = Krows / RPB;

    cudaFuncSetAttribute(auv_step_kernel,
                         cudaFuncAttributeMaxDynamicSharedMemorySize, SMEM_BYTES);
    auv_step_kernel<<<nblk, TPB, SMEM_BYTES>>>(s, a, h0, Wih, Whh, W1, W2, W3, out, Krows);
}

// round 5
// speedup vs baseline: 3.7279x; 1.7374x over previous
#include <cuda_runtime.h>
#include <math.h>

#define RPB 64       // rows per block
#define TPB 256      // threads per block (8 warps)
#define WSTRIDE 132  // padded stride (floats): conflict-free for per-lane LDS.32 frag loads

// Shared layout (floats):
#define OFF_W2   0                         // [128][132] = 16896 (tf32 bits)
#define OFF_Z1   (OFF_W2  + 128*WSTRIDE)   // [64][132]  = 8448  (tf32 bits; staging overlay first)
#define OFF_H1   (OFF_Z1  + RPB*WSTRIDE)   // [64][12]   = 768
#define OFF_SE   (OFF_H1  + 768)           // [64][18]   = 1152
#define OFF_DV   (OFF_SE  + 1152)          // [64][6]    = 384
#define OFF_WIH  (OFF_DV  + 384)           // 252 pad 256
#define OFF_WHH  (OFF_WIH + 256)           // 144
#define SMEM_FLOATS (OFF_WHH + 144)
#define SMEM_BYTES  (SMEM_FLOATS * 4)      // 112,192 B -> 2 CTAs/SM

// staging offsets inside the Z1 region (dead until phase 2)
#define STG_S  (OFF_Z1)          // [64][18]
#define STG_A  (OFF_Z1 + 1152)   // [64][6]
#define STG_H0 (OFF_Z1 + 1536)   // [64][12]

__device__ __forceinline__ float lrelu(float z) { return z >= 0.0f ? z : 0.1f * z; }

__device__ __forceinline__ unsigned f2tf(float f) {
    unsigned u;
    asm("cvt.rna.tf32.f32 %0, %1;" : "=r"(u) : "f"(f));
    return u;
}

__device__ __forceinline__ unsigned long long ffma2(unsigned long long a,
                                                    unsigned long long b,
                                                    unsigned long long c) {
    unsigned long long d;
    asm("fma.rn.f32x2 %0, %1, %2, %3;" : "=l"(d) : "l"(a), "l"(b), "l"(c));
    return d;
}
__device__ __forceinline__ float unpack_sum(unsigned long long u) {
    float2 f;
    asm("mov.b64 {%0, %1}, %2;" : "=f"(f.x), "=f"(f.y) : "l"(u));
    return f.x + f.y;
}

__device__ __forceinline__ void mma_tf32(float* c, const unsigned* a, const unsigned* b) {
    asm volatile(
        "mma.sync.aligned.m16n8k8.row.col.f32.tf32.tf32.f32 "
        "{%0,%1,%2,%3}, {%4,%5,%6,%7}, {%8,%9}, {%0,%1,%2,%3};"
        : "+f"(c[0]), "+f"(c[1]), "+f"(c[2]), "+f"(c[3])
        : "r"(a[0]), "r"(a[1]), "r"(a[2]), "r"(a[3]), "r"(b[0]), "r"(b[1]));
}

__global__ __launch_bounds__(TPB, 2)
void auv_step_kernel(const float* __restrict__ s,
                     const float* __restrict__ a,
                     const float* __restrict__ h0,
                     const float* __restrict__ Wih,
                     const float* __restrict__ Whh,
                     const float* __restrict__ W1,
                     const float* __restrict__ W2,
                     const float* __restrict__ W3,
                     float* __restrict__ out,
                     int Krows)
{
    extern __shared__ float sm[];
    float* sW2  = sm + OFF_W2;
    float* sZ1  = sm + OFF_Z1;
    float* sH1  = sm + OFF_H1;
    float* sSE  = sm + OFF_SE;
    float* sDV  = sm + OFF_DV;
    float* sWih = sm + OFF_WIH;
    float* sWhh = sm + OFF_WHH;

    const int tid = threadIdx.x;
    const long long rowBase = (long long)blockIdx.x * RPB;
    const long long Kll = (long long)Krows;

    // ---- staging: W2 -> tf32 smem (stride 132); small weights; inputs; zero sDV ----
    {
        const float4* W2v = (const float4*)W2;
        #pragma unroll
        for (int i = tid; i < 4096; i += TPB) {
            float4 v = W2v[i];
            uint4 t;
            t.x = f2tf(v.x); t.y = f2tf(v.y); t.z = f2tf(v.z); t.w = f2tf(v.w);
            const int row = i >> 5, c4 = i & 31;
            *(uint4*)(sW2 + row * WSTRIDE + c4 * 4) = t;
        }
        if (tid < 63) ((float4*)sWih)[tid] = ((const float4*)Wih)[tid];
        if (tid < 36) ((float4*)sWhh)[tid] = ((const float4*)Whh)[tid];
        if (tid < 96) ((float4*)sDV)[tid] = make_float4(0.f, 0.f, 0.f, 0.f);
        const float4* sv = (const float4*)(s  + rowBase * 18);
        const float4* av = (const float4*)(a  + rowBase * 6);
        const float4* hv = (const float4*)(h0 + rowBase * 12);
        for (int i = tid; i < 288; i += TPB) ((float4*)(sm + STG_S))[i] = sv[i];
        if (tid < 96)  ((float4*)(sm + STG_A))[tid]  = av[tid];
        if (tid < 192) ((float4*)(sm + STG_H0))[tid] = hv[tid];
    }
    __syncthreads();

    // ---- phase 1: tid<64 -> SE(3); tid 64..255 -> RNN (3 threads/row, 4 outputs each) ----
    if (tid < RPB) {
        const int r = tid;
        const long long g = rowBase + r;
        const float* Sr = sm + STG_S + r * 18;

        const float p0 = Sr[0], p1 = Sr[1], p2 = Sr[2];
        float R[9];
        #pragma unroll
        for (int i = 0; i < 9; i++) R[i] = Sr[3 + i];
        float v[6];
        #pragma unroll
        for (int i = 0; i < 6; i++) v[i] = Sr[12 + i];

        const float DT = 0.1f;
        const float rho0 = v[0] * DT, rho1 = v[1] * DT, rho2 = v[2] * DT;
        const float px = v[3] * DT, py = v[4] * DT, pz = v[5] * DT;
        const float th2 = px * px + py * py + pz * pz;
        const bool small = th2 < 1e-8f;
        const float th2s = small ? 1.0f : th2;
        const float th = sqrtf(th2s);
        const float sth = sinf(th), cth = cosf(th);
        const float A = small ? (1.0f - th2 * (1.0f / 6.0f))  : (sth / th);
        const float B = small ? (0.5f - th2 * (1.0f / 24.0f)) : ((1.0f - cth) / th2s);
        const float C = small ? (1.0f / 6.0f - th2 * (1.0f / 120.0f)) : ((th - sth) / (th2s * th));

        const float S[9]  = {0.0f, -pz, py,  pz, 0.0f, -px,  -py, px, 0.0f};
        float S2[9];
        S2[0] = -(py * py + pz * pz); S2[1] = px * py;              S2[2] = px * pz;
        S2[3] = px * py;              S2[4] = -(px * px + pz * pz); S2[5] = py * pz;
        S2[6] = px * pz;              S2[7] = py * pz;              S2[8] = -(px * px + py * py);

        float Re[9], Vm[9];
        #pragma unroll
        for (int i = 0; i < 9; i++) {
            const float I = (i == 0 || i == 4 || i == 8) ? 1.0f : 0.0f;
            Re[i] = I + A * S[i] + B * S2[i];
            Vm[i] = I + B * S[i] + C * S2[i];
        }
        const float pe0 = Vm[0] * rho0 + Vm[1] * rho1 + Vm[2] * rho2;
        const float pe1 = Vm[3] * rho0 + Vm[4] * rho1 + Vm[5] * rho2;
        const float pe2 = Vm[6] * rho0 + Vm[7] * rho1 + Vm[8] * rho2;

        float Rn[9];
        #pragma unroll
        for (int i = 0; i < 3; i++)
            #pragma unroll
            for (int j = 0; j < 3; j++)
                Rn[i * 3 + j] = R[i * 3 + 0] * Re[0 + j] + R[i * 3 + 1] * Re[3 + j] + R[i * 3 + 2] * Re[6 + j];

        const float pn0 = R[0] * pe0 + R[1] * pe1 + R[2] * pe2 + p0;
        const float pn1 = R[3] * pe0 + R[4] * pe1 + R[5] * pe2 + p1;
        const float pn2 = R[6] * pe0 + R[7] * pe1 + R[8] * pe2 + p2;

        float Ri[9] = {Rn[0], Rn[3], Rn[6], Rn[1], Rn[4], Rn[7], Rn[2], Rn[5], Rn[8]};
        const float pi0 = -(Ri[0] * pn0 + Ri[1] * pn1 + Ri[2] * pn2);
        const float pi1 = -(Ri[3] * pn0 + Ri[4] * pn1 + Ri[5] * pn2);
        const float pi2 = -(Ri[6] * pn0 + Ri[7] * pn1 + Ri[8] * pn2);

        const float u0 = R[0] * v[0] + R[1] * v[1] + R[2] * v[2];
        const float u1 = R[3] * v[0] + R[4] * v[1] + R[5] * v[2];
        const float u2 = R[6] * v[0] + R[7] * v[1] + R[8] * v[2];
        const float w0 = R[0] * v[3] + R[1] * v[4] + R[2] * v[5];
        const float w1 = R[3] * v[3] + R[4] * v[4] + R[5] * v[5];
        const float w2 = R[6] * v[3] + R[7] * v[4] + R[8] * v[5];
        const float t0 = u0 + (p1 * w2 - p2 * w1);
        const float t1 = u1 + (p2 * w0 - p0 * w2);
        const float t2 = u2 + (p0 * w1 - p1 * w0);

        float* se = sSE + r * 18;
        #pragma unroll
        for (int i = 0; i < 9; i++) se[i] = Ri[i];
        se[9]  = pi0; se[10] = pi1; se[11] = pi2;
        se[12] = t0;  se[13] = t1;  se[14] = t2;
        se[15] = w0;  se[16] = w1;  se[17] = w2;

        float* o = out + g * 18;
        o[0] = pn0; o[1] = pn1; o[2] = pn2;
        #pragma unroll
        for (int i = 0; i < 9; i++) o[3 + i] = Rn[i];
    } else {
        const int idx = tid - RPB;            // 0..191
        const int r  = idx / 3;               // row 0..63
        const int j0 = (idx - r * 3) * 4;     // output group: 0,4,8
        const float* Sr  = sm + STG_S  + r * 18;
        const float* Ar  = sm + STG_A  + r * 6;
        const float* H0r = sm + STG_H0 + r * 12;

        float x[21];
        #pragma unroll
        for (int i = 0; i < 15; i++) x[i] = Sr[3 + i];
        #pragma unroll
        for (int i = 0; i < 6; i++) x[15 + i] = Ar[i];
        float h0r[12];
        #pragma unroll
        for (int i = 0; i < 12; i++) h0r[i] = H0r[i];

        #pragma unroll
        for (int jj = 0; jj < 4; jj++) {
            const int j = j0 + jj;
            float acc = 0.0f;
            #pragma unroll
            for (int i = 0; i < 21; i++) acc += x[i] * sWih[j * 21 + i];
            #pragma unroll
            for (int i = 0; i < 12; i++) acc += h0r[i] * sWhh[j * 12 + i];
            sH1[r * 12 + j] = tanhf(acc);
        }
    }
    __syncthreads();

    // ---- phase 2: z1 = lrelu(h1 @ W1^T), rounded to tf32, stored to sZ1 ----
    {
        const int c = tid & 127;
        const float4* w1v = (const float4*)(W1 + c * 12);
        float4 wa = __ldg(w1v), wb = __ldg(w1v + 1), wc4 = __ldg(w1v + 2);
        unsigned long long w[6];
        w[0] = *(unsigned long long*)&wa.x;  w[1] = *(unsigned long long*)&wa.z;
        w[2] = *(unsigned long long*)&wb.x;  w[3] = *(unsigned long long*)&wb.z;
        w[4] = *(unsigned long long*)&wc4.x; w[5] = *(unsigned long long*)&wc4.z;
        #pragma unroll
        for (int r = tid >> 7; r < RPB; r += 2) {
            const unsigned long long* hp = (const unsigned long long*)(sH1 + r * 12);
            unsigned long long acc = 0ull;
            #pragma unroll
            for (int j = 0; j < 6; j++) acc = ffma2(hp[j], w[j], acc);
            sZ1[r * WSTRIDE + c] = __uint_as_float(f2tf(lrelu(unpack_sum(acc))));
        }
    }
    __syncthreads();

    // ---- phase 3: z2 = lrelu(z1 @ W2^T) via tf32 mma.sync; dv = z2 @ W3^T ----
    {
        const int warp = tid >> 5;
        const int lane = tid & 31;
        const int g  = lane >> 2;      // 0..7
        const int tg = lane & 3;       // 0..3
        const int wr = warp & 1;       // row group: rows wr*32 .. +31
        const int wc = warp >> 1;      // col group: cols wc*32 .. +31

        float c[2][4][4];
        #pragma unroll
        for (int mt = 0; mt < 2; mt++)
            #pragma unroll
            for (int nt = 0; nt < 4; nt++)
                #pragma unroll
                for (int q = 0; q < 4; q++) c[mt][nt][q] = 0.0f;

        #pragma unroll 4
        for (int k = 0; k < 128; k += 8) {
            unsigned af[2][4], bf[4][2];
            #pragma unroll
            for (int mt = 0; mt < 2; mt++) {
                const float* ap = sZ1 + (wr * 32 + mt * 16 + g) * WSTRIDE + k + tg;
                af[mt][0] = __float_as_uint(ap[0]);
                af[mt][1] = __float_as_uint(ap[8 * WSTRIDE]);
                af[mt][2] = __float_as_uint(ap[4]);
                af[mt][3] = __float_as_uint(ap[8 * WSTRIDE + 4]);
            }
            #pragma unroll
            for (int nt = 0; nt < 4; nt++) {
                const float* bp = sW2 + (wc * 32 + nt * 8 + g) * WSTRIDE + k + tg;
                bf[nt][0] = __float_as_uint(bp[0]);
                bf[nt][1] = __float_as_uint(bp[4]);
            }
            #pragma unroll
            for (int mt = 0; mt < 2; mt++)
                #pragma unroll
                for (int nt = 0; nt < 4; nt++)
                    mma_tf32(c[mt][nt], af[mt], bf[nt]);
        }

        // lrelu + dv partials (W3 via __ldg; 2-line warp footprint, L1-resident)
        float pd[4][6];     // rows: [mt][0]=base, [mt][1]=+8
        #pragma unroll
        for (int i = 0; i < 4; i++)
            #pragma unroll
            for (int d = 0; d < 6; d++) pd[i][d] = 0.0f;

        #pragma unroll
        for (int nt = 0; nt < 4; nt++) {
            const int col0 = wc * 32 + nt * 8 + 2 * tg;
            #pragma unroll
            for (int d = 0; d < 6; d++) {
                const float w30 = __ldg(W3 + d * 128 + col0);
                const float w31 = __ldg(W3 + d * 128 + col0 + 1);
                #pragma unroll
                for (int mt = 0; mt < 2; mt++) {
                    pd[mt * 2 + 0][d] += lrelu(c[mt][nt][0]) * w30 + lrelu(c[mt][nt][1]) * w31;
                    pd[mt * 2 + 1][d] += lrelu(c[mt][nt][2]) * w30 + lrelu(c[mt][nt][3]) * w31;
                }
            }
        }

        // reduce over the 4 lanes of each g-group
        #pragma unroll
        for (int m = 1; m < 4; m <<= 1)
            #pragma unroll
            for (int i = 0; i < 4; i++)
                #pragma unroll
                for (int d = 0; d < 6; d++)
                    pd[i][d] += __shfl_xor_sync(0xffffffffu, pd[i][d], m);

        if (tg == 0) {
            #pragma unroll
            for (int mt = 0; mt < 2; mt++) {
                const int r0 = wr * 32 + mt * 16 + g;
                #pragma unroll
                for (int d = 0; d < 6; d++) {
                    atomicAdd(sDV + r0 * 6 + d,       pd[mt * 2 + 0][d]);
                    atomicAdd(sDV + (r0 + 8) * 6 + d, pd[mt * 2 + 1][d]);
                }
            }
        }
    }
    __syncthreads();

    // ---- phase 4: v_next ; concurrent hN/dv coalesced dump ----
    if (tid < RPB) {
        const int r = tid;
        const long long g = rowBase + r;
        const float* se  = sSE + r * 18;
        const float* dvp = sDV + r * 6;

        float w6[6];
        #pragma unroll
        for (int i = 0; i < 6; i++) w6[i] = se[12 + i] + dvp[i];

        const float* Ri = se;
        const float pi0 = se[9], pi1 = se[10], pi2 = se[11];

        const float a0 = Ri[0] * w6[0] + Ri[1] * w6[1] + Ri[2] * w6[2];
        const float a1 = Ri[3] * w6[0] + Ri[4] * w6[1] + Ri[5] * w6[2];
        const float a2 = Ri[6] * w6[0] + Ri[7] * w6[1] + Ri[8] * w6[2];
        const float b0 = Ri[0] * w6[3] + Ri[1] * w6[4] + Ri[2] * w6[5];
        const float b1 = Ri[3] * w6[3] + Ri[4] * w6[4] + Ri[5] * w6[5];
        const float b2 = Ri[6] * w6[3] + Ri[7] * w6[4] + Ri[8] * w6[5];

        float* o = out + g * 18;
        o[12] = a0 + (pi1 * b2 - pi2 * b1);
        o[13] = a1 + (pi2 * b0 - pi0 * b2);
        o[14] = a2 + (pi0 * b1 - pi1 * b0);
        o[15] = b0;
        o[16] = b1;
        o[17] = b2;
    } else {
        const int t = tid - RPB;   // 0..191
        float4* d1 = (float4*)(out + Kll * 18 + rowBase * 12);    // hN: 192 float4
        if (t < 96) {
            float4* d2 = (float4*)(out + Kll * 30 + rowBase * 6); // dv: 96 float4
            d2[t] = ((const float4*)sDV)[t];
        }
        d1[t] = ((const float4*)sH1)[t];
    }
}

extern "C" void kernel_launch(void* const* d_in, const int* in_sizes, int n_in,
                              void* d_out, int out_size)
{
    const float* s   = (const float*)d_in[0];
    const float* a   = (const float*)d_in[1];
    const float* h0  = (const float*)d_in[2];
    const float* Wih = (const float*)d_in[3];
    const float* Whh = (const float*)d_in[4];
    const float* W1  = (const float*)d_in[5];
    const float* W2  = (const float*)d_in[6];
    const float* W3  = (const float*)d_in[7];
    float* out = (float*)d_out;

    const int Krows = in_sizes[0] / 18;
    const int nblk = Krows / RPB;

    cudaFuncSetAttribute(auv_step_kernel,
                         cudaFuncAttributeMaxDynamicSharedMemorySize, SMEM_BYTES);
    auv_step_kernel<<<nblk, TPB, SMEM_BYTES>>>(s, a, h0, Wih, Whh, W1, W2, W3, out, Krows);
}

// round 6
// speedup vs baseline: 4.1597x; 1.1158x over previous
#include <cuda_runtime.h>
#include <math.h>

#define RPB 64       // rows per tile
#define TPB 256      // threads per block (8 warps)
#define WSTRIDE 132  // padded stride (floats): conflict-free frag loads

// Shared layout (floats):
#define OFF_W2   0                         // [128][132] = 16896 (tf32 bits, resident)
#define OFF_Z1   (OFF_W2  + 128*WSTRIDE)   // [64][132]  = 8448  (staging overlay before phase 2)
#define OFF_H1   (OFF_Z1  + RPB*WSTRIDE)   // [64][12]   = 768
#define OFF_SE   (OFF_H1  + 768)           // [64][18]   = 1152
#define OFF_DV   (OFF_SE  + 1152)          // [64][6]    = 384
#define OFF_WIH  (OFF_DV  + 384)           // 252 pad 256
#define OFF_WHH  (OFF_WIH + 256)           // 144
#define SMEM_FLOATS (OFF_WHH + 144)
#define SMEM_BYTES  (SMEM_FLOATS * 4)      // 112,192 B -> 2 CTAs/SM

// staging offsets inside the Z1 region (dead until phase 2)
#define STG_S  (OFF_Z1)          // [64][18]
#define STG_A  (OFF_Z1 + 1152)   // [64][6]
#define STG_H0 (OFF_Z1 + 1536)   // [64][12]

__device__ __forceinline__ float lrelu(float z) { return z >= 0.0f ? z : 0.1f * z; }

__device__ __forceinline__ unsigned f2tf(float f) {
    unsigned u;
    asm("cvt.rna.tf32.f32 %0, %1;" : "=r"(u) : "f"(f));
    return u;
}

__device__ __forceinline__ unsigned long long ffma2(unsigned long long a,
                                                    unsigned long long b,
                                                    unsigned long long c) {
    unsigned long long d;
    asm("fma.rn.f32x2 %0, %1, %2, %3;" : "=l"(d) : "l"(a), "l"(b), "l"(c));
    return d;
}
__device__ __forceinline__ float unpack_sum(unsigned long long u) {
    float2 f;
    asm("mov.b64 {%0, %1}, %2;" : "=f"(f.x), "=f"(f.y) : "l"(u));
    return f.x + f.y;
}

__device__ __forceinline__ void mma_tf32(float* c, const unsigned* a, const unsigned* b) {
    asm volatile(
        "mma.sync.aligned.m16n8k8.row.col.f32.tf32.tf32.f32 "
        "{%0,%1,%2,%3}, {%4,%5,%6,%7}, {%8,%9}, {%0,%1,%2,%3};"
        : "+f"(c[0]), "+f"(c[1]), "+f"(c[2]), "+f"(c[3])
        : "r"(a[0]), "r"(a[1]), "r"(a[2]), "r"(a[3]), "r"(b[0]), "r"(b[1]));
}

__global__ __launch_bounds__(TPB, 2)
void auv_step_kernel(const float* __restrict__ s,
                     const float* __restrict__ a,
                     const float* __restrict__ h0,
                     const float* __restrict__ Wih,
                     const float* __restrict__ Whh,
                     const float* __restrict__ W1,
                     const float* __restrict__ W2,
                     const float* __restrict__ W3,
                     float* __restrict__ out,
                     int Krows, int ntiles)
{
    extern __shared__ float sm[];
    float* sW2  = sm + OFF_W2;
    float* sZ1  = sm + OFF_Z1;
    float* sH1  = sm + OFF_H1;
    float* sSE  = sm + OFF_SE;
    float* sDV  = sm + OFF_DV;
    float* sWih = sm + OFF_WIH;
    float* sWhh = sm + OFF_WHH;

    const int tid = threadIdx.x;
    const long long Kll = (long long)Krows;

    // ---- one-time staging: W2 -> tf32 smem; small weights ----
    {
        const float4* W2v = (const float4*)W2;
        #pragma unroll
        for (int i = tid; i < 4096; i += TPB) {
            float4 v = W2v[i];
            uint4 t;
            t.x = f2tf(v.x); t.y = f2tf(v.y); t.z = f2tf(v.z); t.w = f2tf(v.w);
            const int row = i >> 5, c4 = i & 31;
            *(uint4*)(sW2 + row * WSTRIDE + c4 * 4) = t;
        }
        if (tid < 63) ((float4*)sWih)[tid] = ((const float4*)Wih)[tid];
        if (tid < 36) ((float4*)sWhh)[tid] = ((const float4*)Whh)[tid];
    }
    // (first loop-top __syncthreads covers visibility)

    for (int tile = blockIdx.x; tile < ntiles; tile += gridDim.x) {
        const long long rowBase = (long long)tile * RPB;

        // ---- per-tile staging: inputs; zero sDV ----
        {
            const float4* sv = (const float4*)(s  + rowBase * 18);
            const float4* av = (const float4*)(a  + rowBase * 6);
            const float4* hv = (const float4*)(h0 + rowBase * 12);
            for (int i = tid; i < 288; i += TPB) ((float4*)(sm + STG_S))[i] = sv[i];
            if (tid < 96)  ((float4*)(sm + STG_A))[tid]  = av[tid];
            if (tid < 192) ((float4*)(sm + STG_H0))[tid] = hv[tid];
            if (tid < 96)  ((float4*)sDV)[tid] = make_float4(0.f, 0.f, 0.f, 0.f);
        }
        __syncthreads();

        // ---- phase 1: tid<64 -> SE(3); tid 64..255 -> RNN (3 thr/row, 4 outs) ----
        if (tid < RPB) {
            const int r = tid;
            const long long g = rowBase + r;
            const float* Sr = sm + STG_S + r * 18;

            const float p0 = Sr[0], p1 = Sr[1], p2 = Sr[2];
            float R[9];
            #pragma unroll
            for (int i = 0; i < 9; i++) R[i] = Sr[3 + i];
            float v[6];
            #pragma unroll
            for (int i = 0; i < 6; i++) v[i] = Sr[12 + i];

            const float DT = 0.1f;
            const float rho0 = v[0] * DT, rho1 = v[1] * DT, rho2 = v[2] * DT;
            const float px = v[3] * DT, py = v[4] * DT, pz = v[5] * DT;
            const float th2 = px * px + py * py + pz * pz;
            const bool small = th2 < 1e-8f;
            const float th2s = small ? 1.0f : th2;
            const float th = sqrtf(th2s);
            const float sth = sinf(th), cth = cosf(th);
            const float A = small ? (1.0f - th2 * (1.0f / 6.0f))  : (sth / th);
            const float B = small ? (0.5f - th2 * (1.0f / 24.0f)) : ((1.0f - cth) / th2s);
            const float C = small ? (1.0f / 6.0f - th2 * (1.0f / 120.0f)) : ((th - sth) / (th2s * th));

            const float S[9]  = {0.0f, -pz, py,  pz, 0.0f, -px,  -py, px, 0.0f};
            float S2[9];
            S2[0] = -(py * py + pz * pz); S2[1] = px * py;              S2[2] = px * pz;
            S2[3] = px * py;              S2[4] = -(px * px + pz * pz); S2[5] = py * pz;
            S2[6] = px * pz;              S2[7] = py * pz;              S2[8] = -(px * px + py * py);

            float Re[9], Vm[9];
            #pragma unroll
            for (int i = 0; i < 9; i++) {
                const float I = (i == 0 || i == 4 || i == 8) ? 1.0f : 0.0f;
                Re[i] = I + A * S[i] + B * S2[i];
                Vm[i] = I + B * S[i] + C * S2[i];
            }
            const float pe0 = Vm[0] * rho0 + Vm[1] * rho1 + Vm[2] * rho2;
            const float pe1 = Vm[3] * rho0 + Vm[4] * rho1 + Vm[5] * rho2;
            const float pe2 = Vm[6] * rho0 + Vm[7] * rho1 + Vm[8] * rho2;

            float Rn[9];
            #pragma unroll
            for (int i = 0; i < 3; i++)
                #pragma unroll
                for (int j = 0; j < 3; j++)
                    Rn[i * 3 + j] = R[i * 3 + 0] * Re[0 + j] + R[i * 3 + 1] * Re[3 + j] + R[i * 3 + 2] * Re[6 + j];

            const float pn0 = R[0] * pe0 + R[1] * pe1 + R[2] * pe2 + p0;
            const float pn1 = R[3] * pe0 + R[4] * pe1 + R[5] * pe2 + p1;
            const float pn2 = R[6] * pe0 + R[7] * pe1 + R[8] * pe2 + p2;

            float Ri[9] = {Rn[0], Rn[3], Rn[6], Rn[1], Rn[4], Rn[7], Rn[2], Rn[5], Rn[8]};
            const float pi0 = -(Ri[0] * pn0 + Ri[1] * pn1 + Ri[2] * pn2);
            const float pi1 = -(Ri[3] * pn0 + Ri[4] * pn1 + Ri[5] * pn2);
            const float pi2 = -(Ri[6] * pn0 + Ri[7] * pn1 + Ri[8] * pn2);

            const float u0 = R[0] * v[0] + R[1] * v[1] + R[2] * v[2];
            const float u1 = R[3] * v[0] + R[4] * v[1] + R[5] * v[2];
            const float u2 = R[6] * v[0] + R[7] * v[1] + R[8] * v[2];
            const float w0 = R[0] * v[3] + R[1] * v[4] + R[2] * v[5];
            const float w1 = R[3] * v[3] + R[4] * v[4] + R[5] * v[5];
            const float w2 = R[6] * v[3] + R[7] * v[4] + R[8] * v[5];
            const float t0 = u0 + (p1 * w2 - p2 * w1);
            const float t1 = u1 + (p2 * w0 - p0 * w2);
            const float t2 = u2 + (p0 * w1 - p1 * w0);

            float* se = sSE + r * 18;
            #pragma unroll
            for (int i = 0; i < 9; i++) se[i] = Ri[i];
            se[9]  = pi0; se[10] = pi1; se[11] = pi2;
            se[12] = t0;  se[13] = t1;  se[14] = t2;
            se[15] = w0;  se[16] = w1;  se[17] = w2;

            float* o = out + g * 18;
            o[0] = pn0; o[1] = pn1; o[2] = pn2;
            #pragma unroll
            for (int i = 0; i < 9; i++) o[3 + i] = Rn[i];
        } else {
            const int idx = tid - RPB;            // 0..191
            const int r  = idx / 3;               // row 0..63
            const int j0 = (idx - r * 3) * 4;     // output group: 0,4,8
            const float* Sr  = sm + STG_S  + r * 18;
            const float* Ar  = sm + STG_A  + r * 6;
            const float* H0r = sm + STG_H0 + r * 12;

            float x[21];
            #pragma unroll
            for (int i = 0; i < 15; i++) x[i] = Sr[3 + i];
            #pragma unroll
            for (int i = 0; i < 6; i++) x[15 + i] = Ar[i];
            float h0r[12];
            #pragma unroll
            for (int i = 0; i < 12; i++) h0r[i] = H0r[i];

            #pragma unroll
            for (int jj = 0; jj < 4; jj++) {
                const int j = j0 + jj;
                float acc = 0.0f;
                #pragma unroll
                for (int i = 0; i < 21; i++) acc += x[i] * sWih[j * 21 + i];
                #pragma unroll
                for (int i = 0; i < 12; i++) acc += h0r[i] * sWhh[j * 12 + i];
                sH1[r * 12 + j] = tanhf(acc);
            }
        }
        __syncthreads();

        // ---- phase 2: z1 = lrelu(h1 @ W1^T), rounded to tf32 ----
        {
            const int c = tid & 127;
            const float4* w1v = (const float4*)(W1 + c * 12);
            float4 wa = __ldg(w1v), wb = __ldg(w1v + 1), wc4 = __ldg(w1v + 2);
            unsigned long long w[6];
            w[0] = *(unsigned long long*)&wa.x;  w[1] = *(unsigned long long*)&wa.z;
            w[2] = *(unsigned long long*)&wb.x;  w[3] = *(unsigned long long*)&wb.z;
            w[4] = *(unsigned long long*)&wc4.x; w[5] = *(unsigned long long*)&wc4.z;
            #pragma unroll
            for (int r = tid >> 7; r < RPB; r += 2) {
                const unsigned long long* hp = (const unsigned long long*)(sH1 + r * 12);
                unsigned long long acc = 0ull;
                #pragma unroll
                for (int j = 0; j < 6; j++) acc = ffma2(hp[j], w[j], acc);
                sZ1[r * WSTRIDE + c] = __uint_as_float(f2tf(lrelu(unpack_sum(acc))));
            }
        }
        __syncthreads();

        // ---- phase 3: z2 = lrelu(z1 @ W2^T) via tf32 mma.sync; dv = z2 @ W3^T ----
        {
            const int warp = tid >> 5;
            const int lane = tid & 31;
            const int g  = lane >> 2;      // 0..7
            const int tg = lane & 3;       // 0..3
            const int wr = warp & 1;       // rows wr*32 .. +31
            const int wc = warp >> 1;      // cols wc*32 .. +31

            float c[2][4][4];
            #pragma unroll
            for (int mt = 0; mt < 2; mt++)
                #pragma unroll
                for (int nt = 0; nt < 4; nt++)
                    #pragma unroll
                    for (int q = 0; q < 4; q++) c[mt][nt][q] = 0.0f;

            #pragma unroll 4
            for (int k = 0; k < 128; k += 8) {
                unsigned af[2][4], bf[4][2];
                #pragma unroll
                for (int mt = 0; mt < 2; mt++) {
                    const float* ap = sZ1 + (wr * 32 + mt * 16 + g) * WSTRIDE + k + tg;
                    af[mt][0] = __float_as_uint(ap[0]);
                    af[mt][1] = __float_as_uint(ap[8 * WSTRIDE]);
                    af[mt][2] = __float_as_uint(ap[4]);
                    af[mt][3] = __float_as_uint(ap[8 * WSTRIDE + 4]);
                }
                #pragma unroll
                for (int nt = 0; nt < 4; nt++) {
                    const float* bp = sW2 + (wc * 32 + nt * 8 + g) * WSTRIDE + k + tg;
                    bf[nt][0] = __float_as_uint(bp[0]);
                    bf[nt][1] = __float_as_uint(bp[4]);
                }
                #pragma unroll
                for (int mt = 0; mt < 2; mt++)
                    #pragma unroll
                    for (int nt = 0; nt < 4; nt++)
                        mma_tf32(c[mt][nt], af[mt], bf[nt]);
            }

            float pd[4][6];
            #pragma unroll
            for (int i = 0; i < 4; i++)
                #pragma unroll
                for (int d = 0; d < 6; d++) pd[i][d] = 0.0f;

            #pragma unroll
            for (int nt = 0; nt < 4; nt++) {
                const int col0 = wc * 32 + nt * 8 + 2 * tg;
                #pragma unroll
                for (int d = 0; d < 6; d++) {
                    const float w30 = __ldg(W3 + d * 128 + col0);
                    const float w31 = __ldg(W3 + d * 128 + col0 + 1);
                    #pragma unroll
                    for (int mt = 0; mt < 2; mt++) {
                        pd[mt * 2 + 0][d] += lrelu(c[mt][nt][0]) * w30 + lrelu(c[mt][nt][1]) * w31;
                        pd[mt * 2 + 1][d] += lrelu(c[mt][nt][2]) * w30 + lrelu(c[mt][nt][3]) * w31;
                    }
                }
            }

            #pragma unroll
            for (int m = 1; m < 4; m <<= 1)
                #pragma unroll
                for (int i = 0; i < 4; i++)
                    #pragma unroll
                    for (int d = 0; d < 6; d++)
                        pd[i][d] += __shfl_xor_sync(0xffffffffu, pd[i][d], m);

            if (tg == 0) {
                #pragma unroll
                for (int mt = 0; mt < 2; mt++) {
                    const int r0 = wr * 32 + mt * 16 + g;
                    #pragma unroll
                    for (int d = 0; d < 6; d++) {
                        atomicAdd(sDV + r0 * 6 + d,       pd[mt * 2 + 0][d]);
                        atomicAdd(sDV + (r0 + 8) * 6 + d, pd[mt * 2 + 1][d]);
                    }
                }
            }
        }
        __syncthreads();

        // ---- phase 4: v_next ; concurrent hN/dv coalesced dump ----
        if (tid < RPB) {
            const int r = tid;
            const long long g = rowBase + r;
            const float* se  = sSE + r * 18;
            const float* dvp = sDV + r * 6;

            float w6[6];
            #pragma unroll
            for (int i = 0; i < 6; i++) w6[i] = se[12 + i] + dvp[i];

            const float* Ri = se;
            const float pi0 = se[9], pi1 = se[10], pi2 = se[11];

            const float a0 = Ri[0] * w6[0] + Ri[1] * w6[1] + Ri[2] * w6[2];
            const float a1 = Ri[3] * w6[0] + Ri[4] * w6[1] + Ri[5] * w6[2];
            const float a2 = Ri[6] * w6[0] + Ri[7] * w6[1] + Ri[8] * w6[2];
            const float b0 = Ri[0] * w6[3] + Ri[1] * w6[4] + Ri[2] * w6[5];
            const float b1 = Ri[3] * w6[3] + Ri[4] * w6[4] + Ri[5] * w6[5];
            const float b2 = Ri[6] * w6[3] + Ri[7] * w6[4] + Ri[8] * w6[5];

            float* o = out + g * 18;
            o[12] = a0 + (pi1 * b2 - pi2 * b1);
            o[13] = a1 + (pi2 * b0 - pi0 * b2);
            o[14] = a2 + (pi0 * b1 - pi1 * b0);
            o[15] = b0;
            o[16] = b1;
            o[17] = b2;
        } else {
            const int t = tid - RPB;   // 0..191
            float4* d1 = (float4*)(out + Kll * 18 + rowBase * 12);    // hN: 192 float4
            if (t < 96) {
                float4* d2 = (float4*)(out + Kll * 30 + rowBase * 6); // dv: 96 float4
                d2[t] = ((const float4*)sDV)[t];
            }
            d1[t] = ((const float4*)sH1)[t];
        }
        __syncthreads();   // protect staging overlay + sDV before next tile
    }
}

extern "C" void kernel_launch(void* const* d_in, const int* in_sizes, int n_in,
                              void* d_out, int out_size)
{
    const float* s   = (const float*)d_in[0];
    const float* a   = (const float*)d_in[1];
    const float* h0  = (const float*)d_in[2];
    const float* Wih = (const float*)d_in[3];
    const float* Whh = (const float*)d_in[4];
    const float* W1  = (const float*)d_in[5];
    const float* W2  = (const float*)d_in[6];
    const float* W3  = (const float*)d_in[7];
    float* out = (float*)d_out;

    const int Krows  = in_sizes[0] / 18;   // s is [K,1,18]
    const int ntiles = Krows / RPB;

    int dev = 0, nsm = 148;
    cudaGetDevice(&dev);
    cudaDeviceGetAttribute(&nsm, cudaDevAttrMultiProcessorCount, dev);
    int nblk = 2 * nsm;
    if (nblk > ntiles) nblk = ntiles;

    cudaFuncSetAttribute(auv_step_kernel,
                         cudaFuncAttributeMaxDynamicSharedMemorySize, SMEM_BYTES);
    auv_step_kernel<<<nblk, TPB, SMEM_BYTES>>>(s, a, h0, Wih, Whh, W1, W2, W3, out,
                                               Krows, ntiles);
}

// round 9
// speedup vs baseline: 4.3154x; 1.0374x over previous
#include <cuda_runtime.h>
#include <math.h>

#define RPB 64       // rows per tile
#define TPB 256      // threads per block (8 warps)
#define WSTRIDE 132  // padded stride (floats): conflict-free frag loads

// Shared layout (floats):
#define OFF_W2   0                         // [128][132] = 16896 (tf32 bits, resident)
#define OFF_Z1   (OFF_W2  + 128*WSTRIDE)   // [64][132]  = 8448  (staging overlay, rows<18)
#define OFF_H1   (OFF_Z1  + RPB*WSTRIDE)   // [64][12]   = 768
#define OFF_SE   (OFF_H1  + 768)           // [64][18]   = 1152
#define OFF_DV   (OFF_SE  + 1152)          // [64][6]    = 384
#define OFF_WIH  (OFF_DV  + 384)           // 252 pad 256
#define OFF_WHH  (OFF_WIH + 256)           // 144
#define SMEM_FLOATS (OFF_WHH + 144)
#define SMEM_BYTES  (SMEM_FLOATS * 4)      // 112,192 B -> 2 CTAs/SM

// staging offsets inside the Z1 region (consumed only by phase 1)
#define STG_S  (OFF_Z1)          // [64][18] = 288 float4
#define STG_A  (OFF_Z1 + 1152)   // [64][6]  = 96 float4
#define STG_H0 (OFF_Z1 + 1536)   // [64][12] = 192 float4

__device__ __forceinline__ float lrelu(float z) { return z >= 0.0f ? z : 0.1f * z; }

__device__ __forceinline__ float fast_tanh(float x) {
    float e = __expf(2.0f * x);
    return 1.0f - __fdividef(2.0f, e + 1.0f);
}

__device__ __forceinline__ unsigned f2tf(float f) {
    unsigned u;
    asm("cvt.rna.tf32.f32 %0, %1;" : "=r"(u) : "f"(f));
    return u;
}

__device__ __forceinline__ unsigned long long ffma2(unsigned long long a,
                                                    unsigned long long b,
                                                    unsigned long long c) {
    unsigned long long d;
    asm("fma.rn.f32x2 %0, %1, %2, %3;" : "=l"(d) : "l"(a), "l"(b), "l"(c));
    return d;
}
__device__ __forceinline__ float unpack_sum(unsigned long long u) {
    float2 f;
    asm("mov.b64 {%0, %1}, %2;" : "=f"(f.x), "=f"(f.y) : "l"(u));
    return f.x + f.y;
}

__device__ __forceinline__ void mma_tf32(float* c, const unsigned* a, const unsigned* b) {
    asm volatile(
        "mma.sync.aligned.m16n8k8.row.col.f32.tf32.tf32.f32 "
        "{%0,%1,%2,%3}, {%4,%5,%6,%7}, {%8,%9}, {%0,%1,%2,%3};"
        : "+f"(c[0]), "+f"(c[1]), "+f"(c[2]), "+f"(c[3])
        : "r"(a[0]), "r"(a[1]), "r"(a[2]), "r"(a[3]), "r"(b[0]), "r"(b[1]));
}

__global__ __launch_bounds__(TPB, 2)
void auv_step_kernel(const float* __restrict__ s,
                     const float* __restrict__ a,
                     const float* __restrict__ h0,
                     const float* __restrict__ Wih,
                     const float* __restrict__ Whh,
                     const float* __restrict__ W1,
                     const float* __restrict__ W2,
                     const float* __restrict__ W3,
                     float* __restrict__ out,
                     int Krows, int ntiles)
{
    extern __shared__ float sm[];
    float* sW2  = sm + OFF_W2;
    float* sZ1  = sm + OFF_Z1;
    float* sH1  = sm + OFF_H1;
    float* sSE  = sm + OFF_SE;
    float* sDV  = sm + OFF_DV;
    float* sWih = sm + OFF_WIH;
    float* sWhh = sm + OFF_WHH;

    const int tid = threadIdx.x;
    const long long Kll = (long long)Krows;

    // ---- one-time staging: W2 -> tf32 smem; small weights ----
    {
        const float4* W2v = (const float4*)W2;
        #pragma unroll
        for (int i = tid; i < 4096; i += TPB) {
            float4 v = W2v[i];
            uint4 t;
            t.x = f2tf(v.x); t.y = f2tf(v.y); t.z = f2tf(v.z); t.w = f2tf(v.w);
            const int row = i >> 5, c4 = i & 31;
            *(uint4*)(sW2 + row * WSTRIDE + c4 * 4) = t;
        }
        if (tid < 63) ((float4*)sWih)[tid] = ((const float4*)Wih)[tid];
        if (tid < 36) ((float4*)sWhh)[tid] = ((const float4*)Whh)[tid];
    }

    // ---- stage first tile directly ----
    {
        const long long rb0 = (long long)blockIdx.x * RPB;
        const float4* sv = (const float4*)(s  + rb0 * 18);
        const float4* av = (const float4*)(a  + rb0 * 6);
        const float4* hv = (const float4*)(h0 + rb0 * 12);
        for (int i = tid; i < 288; i += TPB) ((float4*)(sm + STG_S))[i] = sv[i];
        if (tid < 96)  ((float4*)(sm + STG_A))[tid]  = av[tid];
        if (tid < 192) ((float4*)(sm + STG_H0))[tid] = hv[tid];
    }

    for (int tile = blockIdx.x; tile < ntiles; tile += gridDim.x) {
        const long long rowBase = (long long)tile * RPB;
        __syncthreads();   // staging (initial or from prev iteration) visible

        // ---- phase 1: tid<64 -> SE(3); tid 64..255 -> RNN (3 thr/row, 4 outs) ----
        if (tid < RPB) {
            const int r = tid;
            const long long g = rowBase + r;
            const float* Sr = sm + STG_S + r * 18;

            const float p0 = Sr[0], p1 = Sr[1], p2 = Sr[2];
            float R[9];
            #pragma unroll
            for (int i = 0; i < 9; i++) R[i] = Sr[3 + i];
            float v[6];
            #pragma unroll
            for (int i = 0; i < 6; i++) v[i] = Sr[12 + i];

            const float DT = 0.1f;
            const float rho0 = v[0] * DT, rho1 = v[1] * DT, rho2 = v[2] * DT;
            const float px = v[3] * DT, py = v[4] * DT, pz = v[5] * DT;
            const float th2 = px * px + py * py + pz * pz;
            const bool small = th2 < 1e-8f;
            const float th2s = small ? 1.0f : th2;
            const float th = sqrtf(th2s);
            const float sth = __sinf(th), cth = __cosf(th);
            const float A = small ? (1.0f - th2 * (1.0f / 6.0f))  : __fdividef(sth, th);
            const float B = small ? (0.5f - th2 * (1.0f / 24.0f)) : __fdividef(1.0f - cth, th2s);
            const float C = small ? (1.0f / 6.0f - th2 * (1.0f / 120.0f))
                                  : __fdividef(th - sth, th2s * th);

            const float S[9]  = {0.0f, -pz, py,  pz, 0.0f, -px,  -py, px, 0.0f};
            float S2[9];
            S2[0] = -(py * py + pz * pz); S2[1] = px * py;              S2[2] = px * pz;
            S2[3] = px * py;              S2[4] = -(px * px + pz * pz); S2[5] = py * pz;
            S2[6] = px * pz;              S2[7] = py * pz;              S2[8] = -(px * px + py * py);

            float Re[9], Vm[9];
            #pragma unroll
            for (int i = 0; i < 9; i++) {
                const float I = (i == 0 || i == 4 || i == 8) ? 1.0f : 0.0f;
                Re[i] = I + A * S[i] + B * S2[i];
                Vm[i] = I + B * S[i] + C * S2[i];
            }
            const float pe0 = Vm[0] * rho0 + Vm[1] * rho1 + Vm[2] * rho2;
            const float pe1 = Vm[3] * rho0 + Vm[4] * rho1 + Vm[5] * rho2;
            const float pe2 = Vm[6] * rho0 + Vm[7] * rho1 + Vm[8] * rho2;

            float Rn[9];
            #pragma unroll
            for (int i = 0; i < 3; i++)
                #pragma unroll
                for (int j = 0; j < 3; j++)
                    Rn[i * 3 + j] = R[i * 3 + 0] * Re[0 + j] + R[i * 3 + 1] * Re[3 + j] + R[i * 3 + 2] * Re[6 + j];

            const float pn0 = R[0] * pe0 + R[1] * pe1 + R[2] * pe2 + p0;
            const float pn1 = R[3] * pe0 + R[4] * pe1 + R[5] * pe2 + p1;
            const float pn2 = R[6] * pe0 + R[7] * pe1 + R[8] * pe2 + p2;

            float Ri[9] = {Rn[0], Rn[3], Rn[6], Rn[1], Rn[4], Rn[7], Rn[2], Rn[5], Rn[8]};
            const float pi0 = -(Ri[0] * pn0 + Ri[1] * pn1 + Ri[2] * pn2);
            const float pi1 = -(Ri[3] * pn0 + Ri[4] * pn1 + Ri[5] * pn2);
            const float pi2 = -(Ri[6] * pn0 + Ri[7] * pn1 + Ri[8] * pn2);

            const float u0 = R[0] * v[0] + R[1] * v[1] + R[2] * v[2];
            const float u1 = R[3] * v[0] + R[4] * v[1] + R[5] * v[2];
            const float u2 = R[6] * v[0] + R[7] * v[1] + R[8] * v[2];
            const float w0 = R[0] * v[3] + R[1] * v[4] + R[2] * v[5];
            const float w1 = R[3] * v[3] + R[4] * v[4] + R[5] * v[5];
            const float w2 = R[6] * v[3] + R[7] * v[4] + R[8] * v[5];
            const float t0 = u0 + (p1 * w2 - p2 * w1);
            const float t1 = u1 + (p2 * w0 - p0 * w2);
            const float t2 = u2 + (p0 * w1 - p1 * w0);

            float* se = sSE + r * 18;
            #pragma unroll
            for (int i = 0; i < 9; i++) se[i] = Ri[i];
            se[9]  = pi0; se[10] = pi1; se[11] = pi2;
            se[12] = t0;  se[13] = t1;  se[14] = t2;
            se[15] = w0;  se[16] = w1;  se[17] = w2;

            float* o = out + g * 18;
            o[0] = pn0; o[1] = pn1; o[2] = pn2;
            #pragma unroll
            for (int i = 0; i < 9; i++) o[3 + i] = Rn[i];
        } else {
            const int idx = tid - RPB;            // 0..191
            const int r  = idx / 3;               // row 0..63
            const int j0 = (idx - r * 3) * 4;     // output group: 0,4,8
            const float* Sr  = sm + STG_S  + r * 18;
            const float* Ar  = sm + STG_A  + r * 6;
            const float* H0r = sm + STG_H0 + r * 12;

            float x[21];
            #pragma unroll
            for (int i = 0; i < 15; i++) x[i] = Sr[3 + i];
            #pragma unroll
            for (int i = 0; i < 6; i++) x[15 + i] = Ar[i];
            float h0r[12];
            #pragma unroll
            for (int i = 0; i < 12; i++) h0r[i] = H0r[i];

            #pragma unroll
            for (int jj = 0; jj < 4; jj++) {
                const int j = j0 + jj;
                float acc = 0.0f;
                #pragma unroll
                for (int i = 0; i < 21; i++) acc += x[i] * sWih[j * 21 + i];
                #pragma unroll
                for (int i = 0; i < 12; i++) acc += h0r[i] * sWhh[j * 12 + i];
                sH1[r * 12 + j] = fast_tanh(acc);
            }
        }
        __syncthreads();

        // ---- phase 2: z1 -> tf32 ; prefetch next tile (FULL coverage) ; zero sDV ----
        const int tile2 = tile + gridDim.x;
        const bool hasNext = tile2 < ntiles;
        float4 pf0a = make_float4(0.f, 0.f, 0.f, 0.f);
        float4 pf0b = pf0a, pf1 = pf0a, pf2 = pf0a;
        {
            if (hasNext) {
                const long long rb2 = (long long)tile2 * RPB;
                const float4* sv = (const float4*)(s + rb2 * 18);
                pf0a = __ldg(sv + tid);                             // 0..255
                if (tid < 32)  pf0b = __ldg(sv + 256 + tid);        // 256..287
                if (tid < 96)  pf1 = __ldg((const float4*)(a  + rb2 * 6)  + tid);
                if (tid < 192) pf2 = __ldg((const float4*)(h0 + rb2 * 12) + tid);
            }
            if (tid < 96) ((float4*)sDV)[tid] = make_float4(0.f, 0.f, 0.f, 0.f);

            const int c = tid & 127;
            const float4* w1v = (const float4*)(W1 + c * 12);
            float4 wa = __ldg(w1v), wb = __ldg(w1v + 1), wc4 = __ldg(w1v + 2);
            unsigned long long w[6];
            w[0] = *(unsigned long long*)&wa.x;  w[1] = *(unsigned long long*)&wa.z;
            w[2] = *(unsigned long long*)&wb.x;  w[3] = *(unsigned long long*)&wb.z;
            w[4] = *(unsigned long long*)&wc4.x; w[5] = *(unsigned long long*)&wc4.z;
            #pragma unroll
            for (int r = tid >> 7; r < RPB; r += 2) {
                const unsigned long long* hp = (const unsigned long long*)(sH1 + r * 12);
                unsigned long long acc = 0ull;
                #pragma unroll
                for (int j = 0; j < 6; j++) acc = ffma2(hp[j], w[j], acc);
                sZ1[r * WSTRIDE + c] = __uint_as_float(f2tf(lrelu(unpack_sum(acc))));
            }
        }
        __syncthreads();

        // ---- phase 3: z2 = lrelu(z1 @ W2^T) via tf32 mma.sync; dv = z2 @ W3^T ----
        {
            const int warp = tid >> 5;
            const int lane = tid & 31;
            const int g  = lane >> 2;
            const int tg = lane & 3;
            const int wr = warp & 1;
            const int wc = warp >> 1;

            float c[2][4][4];
            #pragma unroll
            for (int mt = 0; mt < 2; mt++)
                #pragma unroll
                for (int nt = 0; nt < 4; nt++)
                    #pragma unroll
                    for (int q = 0; q < 4; q++) c[mt][nt][q] = 0.0f;

            #pragma unroll 4
            for (int k = 0; k < 128; k += 8) {
                unsigned af[2][4], bf[4][2];
                #pragma unroll
                for (int mt = 0; mt < 2; mt++) {
                    const float* ap = sZ1 + (wr * 32 + mt * 16 + g) * WSTRIDE + k + tg;
                    af[mt][0] = __float_as_uint(ap[0]);
                    af[mt][1] = __float_as_uint(ap[8 * WSTRIDE]);
                    af[mt][2] = __float_as_uint(ap[4]);
                    af[mt][3] = __float_as_uint(ap[8 * WSTRIDE + 4]);
                }
                #pragma unroll
                for (int nt = 0; nt < 4; nt++) {
                    const float* bp = sW2 + (wc * 32 + nt * 8 + g) * WSTRIDE + k + tg;
                    bf[nt][0] = __float_as_uint(bp[0]);
                    bf[nt][1] = __float_as_uint(bp[4]);
                }
                #pragma unroll
                for (int mt = 0; mt < 2; mt++)
                    #pragma unroll
                    for (int nt = 0; nt < 4; nt++)
                        mma_tf32(c[mt][nt], af[mt], bf[nt]);
            }

            float pd[4][6];
            #pragma unroll
            for (int i = 0; i < 4; i++)
                #pragma unroll
                for (int d = 0; d < 6; d++) pd[i][d] = 0.0f;

            #pragma unroll
            for (int nt = 0; nt < 4; nt++) {
                const int col0 = wc * 32 + nt * 8 + 2 * tg;
                #pragma unroll
                for (int d = 0; d < 6; d++) {
                    const float w30 = __ldg(W3 + d * 128 + col0);
                    const float w31 = __ldg(W3 + d * 128 + col0 + 1);
                    #pragma unroll
                    for (int mt = 0; mt < 2; mt++) {
                        pd[mt * 2 + 0][d] += lrelu(c[mt][nt][0]) * w30 + lrelu(c[mt][nt][1]) * w31;
                        pd[mt * 2 + 1][d] += lrelu(c[mt][nt][2]) * w30 + lrelu(c[mt][nt][3]) * w31;
                    }
                }
            }

            #pragma unroll
            for (int m = 1; m < 4; m <<= 1)
                #pragma unroll
                for (int i = 0; i < 4; i++)
                    #pragma unroll
                    for (int d = 0; d < 6; d++)
                        pd[i][d] += __shfl_xor_sync(0xffffffffu, pd[i][d], m);

            if (tg == 0) {
                #pragma unroll
                for (int mt = 0; mt < 2; mt++) {
                    const int r0 = wr * 32 + mt * 16 + g;
                    #pragma unroll
                    for (int d = 0; d < 6; d++) {
                        atomicAdd(sDV + r0 * 6 + d,       pd[mt * 2 + 0][d]);
                        atomicAdd(sDV + (r0 + 8) * 6 + d, pd[mt * 2 + 1][d]);
                    }
                }
            }
        }
        __syncthreads();

        // ---- phase 4: v_next ; phase 5: hN/dv dump ; store prefetched staging ----
        if (tid < RPB) {
            const int r = tid;
            const long long g = rowBase + r;
            const float* se  = sSE + r * 18;
            const float* dvp = sDV + r * 6;

            float w6[6];
            #pragma unroll
            for (int i = 0; i < 6; i++) w6[i] = se[12 + i] + dvp[i];

            const float* Ri = se;
            const float pi0 = se[9], pi1 = se[10], pi2 = se[11];

            const float a0 = Ri[0] * w6[0] + Ri[1] * w6[1] + Ri[2] * w6[2];
            const float a1 = Ri[3] * w6[0] + Ri[4] * w6[1] + Ri[5] * w6[2];
            const float a2 = Ri[6] * w6[0] + Ri[7] * w6[1] + Ri[8] * w6[2];
            const float b0 = Ri[0] * w6[3] + Ri[1] * w6[4] + Ri[2] * w6[5];
            const float b1 = Ri[3] * w6[3] + Ri[4] * w6[4] + Ri[5] * w6[5];
            const float b2 = Ri[6] * w6[3] + Ri[7] * w6[4] + Ri[8] * w6[5];

            float* o = out + g * 18;
            o[12] = a0 + (pi1 * b2 - pi2 * b1);
            o[13] = a1 + (pi2 * b0 - pi0 * b2);
            o[14] = a2 + (pi0 * b1 - pi1 * b0);
            o[15] = b0;
            o[16] = b1;
            o[17] = b2;
        } else {
            const int t = tid - RPB;   // 0..191
            float4* d1 = (float4*)(out + Kll * 18 + rowBase * 12);    // hN: 192 float4
            if (t < 96) {
                float4* d2 = (float4*)(out + Kll * 30 + rowBase * 6); // dv: 96 float4
                d2[t] = ((const float4*)sDV)[t];
            }
            d1[t] = ((const float4*)sH1)[t];
        }
        if (hasNext) {   // staging region free (phase 3 done); consumed by p1 next iter
            ((float4*)(sm + STG_S))[tid] = pf0a;                       // 0..255
            if (tid < 32)  ((float4*)(sm + STG_S))[256 + tid] = pf0b;  // 256..287
            if (tid < 96)  ((float4*)(sm + STG_A))[tid]  = pf1;
            if (tid < 192) ((float4*)(sm + STG_H0))[tid] = pf2;
        }
        // loop-top __syncthreads() publishes staging for phase 1
    }
}

extern "C" void kernel_launch(void* const* d_in, const int* in_sizes, int n_in,
                              void* d_out, int out_size)
{
    const float* s   = (const float*)d_in[0];
    const float* a   = (const float*)d_in[1];
    const float* h0  = (const float*)d_in[2];
    const float* Wih = (const float*)d_in[3];
    const float* Whh = (const float*)d_in[4];
    const float* W1  = (const float*)d_in[5];
    const float* W2  = (const float*)d_in[6];
    const float* W3  = (const float*)d_in[7];
    float* out = (float*)d_out;

    const int Krows  = in_sizes[0] / 18;   // s is [K,1,18]
    const int ntiles = Krows / RPB;

    int dev = 0, nsm = 148;
    cudaGetDevice(&dev);
    cudaDeviceGetAttribute(&nsm, cudaDevAttrMultiProcessorCount, dev);
    int nblk = 2 * nsm;
    if (nblk > ntiles) nblk = ntiles;

    cudaFuncSetAttribute(auv_step_kernel,
                         cudaFuncAttributeMaxDynamicSharedMemorySize, SMEM_BYTES);
    auv_step_kernel<<<nblk, TPB, SMEM_BYTES>>>(s, a, h0, Wih, Whh, W1, W2, W3, out,
                                               Krows, ntiles);
}